// round 9
// baseline (speedup 1.0000x reference)
#include <cuda_runtime.h>

// Reference collapses: softmax(const(-9e15)) == uniform 1/N  =>  adj/a/e dead.
//   out[i,:] = relu( (colsum(h) @ W) / N )  -- one 64-float row broadcast 8192x.
// One kernel, grid 256 x 1024 (2 blocks/SM, 100% occupancy at 32 regs):
//   A: partial column sums (4 float4 loads/thread; MLP from 64 warps/SM)
//   B: per-block projection through W -> g_pproj[b]
//   C: ticket; last-arriving block reduces 256x64 partials, relu -> g_row, flag
//   D: all blocks spin on one flag, broadcast 2MB output.

#define N_ROWSC 8192
#define F_INC   512
#define F_OUTC  64
#define GRID    256
#define THREADS 1024
#define TOTAL_F4 (N_ROWSC * F_INC / 4)        // 1,048,576
#define STRIDE   (GRID * THREADS)             // 262,144 (multiple of 128)
#define LOADS_PT (TOTAL_F4 / STRIDE)          // 4 (exact)
#define OUT_F4   (N_ROWSC * F_OUTC / 4)       // 131,072

__device__ float g_pproj[GRID * F_OUTC];          // 64 KB per-block projections
__device__ float g_row[F_OUTC];
__device__ unsigned long long g_cnt;              // monotonic across replays
__device__ volatile unsigned long long g_flag;    // epoch of completed row

__global__ __launch_bounds__(THREADS)
void gat_kernel(const float4* __restrict__ h4,
                const float*  __restrict__ W,
                const float4* __restrict__ W4,
                float4*       __restrict__ out)
{
    __shared__ float4 s4[THREADS];            // 16 KB
    __shared__ float  sf[F_INC];              // 2 KB block colsum
    __shared__ float  pp[16 * F_OUTC];        // 4 KB
    __shared__ float4 srow4[F_OUTC / 4];      // 256 B
    __shared__ unsigned long long s_ticket;

    const int t = threadIdx.x;
    const int b = blockIdx.x;

    // Warm W (131 KB = 32768 float4) into L2; blocks 0..31 cover it exactly.
    if (b < 32) {
        float4 w = __ldcg(&W4[b * THREADS + t]);
        asm volatile("" :: "f"(w.x), "f"(w.y), "f"(w.z), "f"(w.w));
    }

    // ---- A: partial column sums; 4 independent float4 loads per thread ----
    {
        const int gid = b * THREADS + t;      // stride mult of 128 -> colgrp = t & 127
        float4 v[LOADS_PT];
        #pragma unroll
        for (int k = 0; k < LOADS_PT; ++k)
            v[k] = h4[gid + k * STRIDE];
        float4 acc = v[0];
        #pragma unroll
        for (int k = 1; k < LOADS_PT; ++k) {  // fixed order -> deterministic
            acc.x += v[k].x; acc.y += v[k].y; acc.z += v[k].z; acc.w += v[k].w;
        }
        s4[t] = acc;
    }
    __syncthreads();
    if (t < 128) {                            // 8 partials per column group, fixed order
        float4 a = s4[t];
        #pragma unroll
        for (int j = 1; j < 8; ++j) {
            float4 v = s4[t + 128 * j];
            a.x += v.x; a.y += v.y; a.z += v.z; a.w += v.w;
        }
        sf[t * 4 + 0] = a.x; sf[t * 4 + 1] = a.y;
        sf[t * 4 + 2] = a.z; sf[t * 4 + 3] = a.w;
    }
    __syncthreads();

    // ---- B: project local colsum through W (col = t&63, 16 k-slices of 32) ----
    {
        const int col = t & 63;
        const int sl  = t >> 6;               // 0..15
        float o = 0.f;
        #pragma unroll 8
        for (int i = 0; i < 32; ++i) {
            const int k = sl * 32 + i;
            o = fmaf(sf[k], W[k * F_OUTC + col], o);   // W is L2-warm, coalesced
        }
        pp[sl * F_OUTC + col] = o;
    }
    __syncthreads();
    if (t < F_OUTC) {                         // fixed combine order
        float v = 0.f;
        #pragma unroll
        for (int sl = 0; sl < 16; ++sl) v += pp[sl * F_OUTC + t];
        g_pproj[b * F_OUTC + t] = v;
    }
    __threadfence();
    __syncthreads();

    if (t == 0) s_ticket = atomicAdd(&g_cnt, 1ULL);
    __syncthreads();
    const unsigned long long ticket = s_ticket;
    const unsigned long long launch = ticket / GRID;   // replay epoch

    if (ticket % GRID == GRID - 1) {
        // ---- C: last arrival reduces 256x64 projections (64 KB, L2) ----
        {
            const int col = t & 63;
            const int sl  = t >> 6;           // 16 slices x 16 blocks
            float v = 0.f;
            #pragma unroll
            for (int j = 0; j < GRID / 16; ++j)
                v += __ldcg(&g_pproj[(sl * (GRID / 16) + j) * F_OUTC + col]);
            pp[sl * F_OUTC + col] = v;
        }
        __syncthreads();
        if (t < F_OUTC) {                     // fixed combine order
            float v = 0.f;
            #pragma unroll
            for (int sl = 0; sl < 16; ++sl) v += pp[sl * F_OUTC + t];
            v *= (1.0f / (float)N_ROWSC);
            g_row[t] = fmaxf(v, 0.0f);
        }
        __threadfence();
        __syncthreads();
        if (t == 0) g_flag = launch + 1;      // release (fence above)
    } else {
        // ---- Waiters: single plain-load spin on one word (no RMW) ----
        if (t == 0) {
            while (g_flag < launch + 1) __nanosleep(64);
            __threadfence();                  // acquire
        }
        __syncthreads();
    }

    // ---- D: broadcast; each block writes 512 float4 (threads 0..511) ----
    if (t < F_OUTC / 4) srow4[t] = __ldcg(((const float4*)g_row) + t);
    __syncthreads();
    if (t < OUT_F4 / GRID) {                  // 512 per block
        const int idx = b * (OUT_F4 / GRID) + t;
        out[idx] = srow4[t & 15];             // 512 mult of 16 -> colgrp = t & 15
    }
}

extern "C" void kernel_launch(void* const* d_in, const int* in_sizes, int n_in,
                              void* d_out, int out_size) {
    (void)in_sizes; (void)n_in; (void)out_size;
    const float* h = (const float*)d_in[0];   // (8192, 512) fp32
    // d_in[1] = adj (8192,8192) -- dead code, never read
    const float* W = (const float*)d_in[2];   // (512, 64) fp32
    // d_in[3] = a (128,1)       -- dead code, never read
    float* out = (float*)d_out;               // (8192, 64) fp32

    gat_kernel<<<GRID, THREADS>>>((const float4*)h, W, (const float4*)W,
                                  (float4*)out);
}